// round 13
// baseline (speedup 1.0000x reference)
#include <cuda_runtime.h>

#define T_SEQ 2048
#define I_IN 7
#define H_DIM 64
#define G_DIM 256   // 4*H
#define B_SZ 256
#define O_DIM 3

using u64 = unsigned long long;

// ---------- packed f32x2 helpers (Blackwell FFMA2 path) ----------
__device__ __forceinline__ u64 pack2(float lo, float hi) {
    u64 r;
    asm("mov.b64 %0, {%1, %2};" : "=l"(r) : "f"(lo), "f"(hi));
    return r;
}
__device__ __forceinline__ void unpack2(u64 v, float& lo, float& hi) {
    asm("mov.b64 {%0, %1}, %2;" : "=f"(lo), "=f"(hi) : "l"(v));
}
__device__ __forceinline__ void ffma2(u64& acc, u64 a, u64 b) {
    asm("fma.rn.f32x2 %0, %1, %2, %0;" : "+l"(acc) : "l"(a), "l"(b));
}
__device__ __forceinline__ u64 add2(u64 a, u64 b) {
    u64 r;
    asm("add.rn.f32x2 %0, %1, %2;" : "=l"(r) : "l"(a), "l"(b));
    return r;
}

// ---------- activations ----------
__device__ __forceinline__ float tanh_fast(float x) {      // MUFU.TANH
    float r;
    asm("tanh.approx.f32 %0, %1;" : "=f"(r) : "f"(x));
    return r;
}
__device__ __forceinline__ float sigm(float x) {           // accurate, bwd kernel only
    return __fdividef(1.0f, 1.0f + __expf(-x));
}

// Forward final hidden state, written by kernel1 and read by kernel2.
__device__ float g_hF[B_SZ * H_DIM];

// ---------- shared memory (dynamic), one batch element per CTA ----------
struct Smem {
    float xs[T_SEQ][8];     // xs[t][i], i<7 valid, [7] zero pad.   65536 B
    float hs[2][H_DIM];     // ping-pong h state.                     512 B
};                          // total 66048 B -> 2 CTAs/SM

__global__ void __launch_bounds__(256, 2)
lstm_fwd_kernel(const float* __restrict__ x,
                const float* __restrict__ W_ih,
                const float* __restrict__ W_hh,
                const float* __restrict__ b_ih,
                const float* __restrict__ b_hh) {
    extern __shared__ Smem sh[];
    Smem& s = sh[0];

    const int tid = threadIdx.x;
    const int b = blockIdx.x;
    const int w = tid >> 5;
    const int l = tid & 31;
    const int kh = l >> 4;                // k-half: 0 -> k[0:32), 1 -> k[32:64)
    const int gp = (l >> 3) & 1;          // 0: owns (i,f); 1: owns (g,o)
    const int unit = w * 8 + (l & 7);     // hidden unit 0..63
    const int rowA = (gp ? 2 * H_DIM : 0) + unit;        // i or g
    const int rowB = (gp ? 3 * H_DIM : H_DIM) + unit;    // f or o
    const int rowP = kh ? rowB : rowA;    // this lane's iproj row

    // ---- stage this batch element's x into smem ----
    {
        const float* xb = x + (size_t)b * T_SEQ * I_IN;
        for (int idx = tid; idx < T_SEQ * I_IN; idx += 256) {
            int t = idx / I_IN;
            int i = idx - t * I_IN;
            s.xs[t][i] = xb[idx];
        }
        for (int t = tid; t < T_SEQ; t += 256) s.xs[t][7] = 0.f;
        if (tid < 2 * H_DIM) ((float*)s.hs)[tid] = 0.f;
    }

    // ---- per-thread weights: two half-rows of W_hh + one full W_ih row ----
    u64 WkA[16], WkB[16];
    {
        const ulonglong2* wpA =
            reinterpret_cast<const ulonglong2*>(W_hh + rowA * H_DIM + kh * 32);
        const ulonglong2* wpB =
            reinterpret_cast<const ulonglong2*>(W_hh + rowB * H_DIM + kh * 32);
#pragma unroll
        for (int q = 0; q < 8; q++) {
            ulonglong2 vA = wpA[q];
            WkA[2 * q] = vA.x; WkA[2 * q + 1] = vA.y;
            ulonglong2 vB = wpB[q];
            WkB[2 * q] = vB.x; WkB[2 * q + 1] = vB.y;
        }
    }
    u64 WiP[4];
    {
        float wv[8];
#pragma unroll
        for (int i = 0; i < 7; i++) wv[i] = W_ih[rowP * I_IN + i];
        wv[7] = 0.f;
#pragma unroll
        for (int q = 0; q < 4; q++) WiP[q] = pack2(wv[2 * q], wv[2 * q + 1]);
    }
    const float biasP = b_ih[rowP] + b_hh[rowP];

    // activation params for the tail lanes (l < 16):
    // rowA is i (sigmoid) for gp=0, g (tanh) for gp=1; rowB always sigmoid.
    const float sA = gp ? 1.0f : 0.5f;
    const float aA = gp ? 1.0f : 0.5f;
    const float bA = gp ? 0.0f : 0.5f;

    float c_state = 0.f;                  // valid on lanes l < 8

    __syncthreads();

    // input projection + bias for own row (packed along i)
    auto iproj = [&](int t) -> float {
        u64 acc = 0ull;
        const ulonglong2* xp = reinterpret_cast<const ulonglong2*>(s.xs[t]);
        ulonglong2 v0 = xp[0], v1 = xp[1];
        ffma2(acc, WiP[0], v0.x);
        ffma2(acc, WiP[1], v0.y);
        ffma2(acc, WiP[2], v1.x);
        ffma2(acc, WiP[3], v1.y);
        float lo, hi;
        unpack2(acc, lo, hi);
        return (lo + hi) + biasP;
    };

    float accP = iproj(0);

    for (int t = 0; t < T_SEQ; t++) {
        // ---- half-row recurrent dots (16 FFMA2 each, 2 accums each) ----
        u64 a0 = 0ull, a1 = 0ull, b0 = 0ull, b1 = 0ull;
        const ulonglong2* hp =
            reinterpret_cast<const ulonglong2*>(s.hs[t & 1]) + kh * 8;
#pragma unroll
        for (int q = 0; q < 4; q++) {
            ulonglong2 v0 = hp[2 * q];
            ulonglong2 v1 = hp[2 * q + 1];
            ffma2(a0, WkA[4 * q + 0], v0.x);
            ffma2(a0, WkA[4 * q + 1], v0.y);
            ffma2(b0, WkB[4 * q + 0], v0.x);
            ffma2(b0, WkB[4 * q + 1], v0.y);
            ffma2(a1, WkA[4 * q + 2], v1.x);
            ffma2(a1, WkA[4 * q + 3], v1.y);
            ffma2(b1, WkB[4 * q + 2], v1.x);
            ffma2(b1, WkB[4 * q + 3], v1.y);
        }
        float al, ah, bl, bh;
        unpack2(add2(a0, a1), al, ah);
        unpack2(add2(b0, b1), bl, bh);
        float pA = al + ah;
        float pB = bl + bh;
        // fold own iproj (row A for kh=0, row B for kh=1)
        if (kh == 0) pA += accP; else pB += accP;

        // ---- k-half combine: partner is lane xor 16 ----
        float rA = __shfl_xor_sync(0xFFFFFFFFu, pA, 16);
        float rB = __shfl_xor_sync(0xFFFFFFFFu, pB, 16);

        if (l < 16) {
            float zA = pA + rA;
            float zB = pB + rB;
            // activations: sigma(z) = 0.5 + 0.5*tanh(0.5 z); tanh for g-row
            float actA = fmaf(aA, tanh_fast(sA * zA), bA);
            float actB = fmaf(0.5f, tanh_fast(0.5f * zB), 0.5f);
            // gate-pair exchange among lanes 0..15: partner is lane xor 8
            float gA = __shfl_xor_sync(0x0000FFFFu, actA, 8);
            float gB = __shfl_xor_sync(0x0000FFFFu, actB, 8);
            if (l < 8) {
                // own: actA=i, actB=f ; received: gA=g, gB=o
                c_state = fmaf(actB, c_state, actA * gA);
                s.hs[(t + 1) & 1][unit] = gB * tanh_fast(c_state);
            }
        }

        // ---- next-step input projection (off the critical path) ----
        int tn = (t + 1 < T_SEQ) ? (t + 1) : t;   // clamp; last iter unused
        accP = iproj(tn);

        __syncthreads();   // single barrier per step
    }

    // final h is in buffer T_SEQ & 1 == 0
    if (tid < H_DIM) g_hF[b * H_DIM + tid] = s.hs[0][tid];
}

// One backward LSTM step (from zero state on x[:,T-1,:]) + final linear.
__global__ void __launch_bounds__(256)
lstm_bwd_out_kernel(const float* __restrict__ x,
                    const float* __restrict__ W_ih_b,
                    const float* __restrict__ b_ih_b,
                    const float* __restrict__ b_hh_b,
                    const float* __restrict__ W_lin,
                    const float* __restrict__ b_lin,
                    float* __restrict__ out) {
    __shared__ float zs[G_DIM];
    __shared__ float hb[H_DIM];
    const int b = blockIdx.x;
    const int g = threadIdx.x;

    const float* xt = x + ((size_t)b * T_SEQ + (T_SEQ - 1)) * I_IN;
    float z = b_ih_b[g] + b_hh_b[g];
#pragma unroll
    for (int i = 0; i < I_IN; i++) z += W_ih_b[g * I_IN + i] * xt[i];
    zs[g] = z;
    __syncthreads();

    if (g < H_DIM) {
        float ig = sigm(zs[g]);
        float gg = tanhf(zs[2 * H_DIM + g]);
        float og = sigm(zs[3 * H_DIM + g]);
        float c = ig * gg;              // f * c_prev = 0 at first step
        hb[g] = og * tanhf(c);
    }
    __syncthreads();

    if (g < O_DIM) {
        float acc = b_lin[g];
        const float* wrow = W_lin + g * (2 * H_DIM);
        const float* hf = g_hF + b * H_DIM;
#pragma unroll 8
        for (int j = 0; j < H_DIM; j++) acc += wrow[j] * hf[j];
#pragma unroll 8
        for (int j = 0; j < H_DIM; j++) acc += wrow[H_DIM + j] * hb[j];
        out[b * O_DIM + g] = acc;
    }
}

extern "C" void kernel_launch(void* const* d_in, const int* in_sizes, int n_in,
                              void* d_out, int out_size) {
    const float* x      = (const float*)d_in[0];
    const float* Wih_f  = (const float*)d_in[1];
    const float* Whh_f  = (const float*)d_in[2];
    const float* bih_f  = (const float*)d_in[3];
    const float* bhh_f  = (const float*)d_in[4];
    const float* Wih_b  = (const float*)d_in[5];
    const float* bih_b  = (const float*)d_in[7];
    const float* bhh_b  = (const float*)d_in[8];
    const float* Wlin   = (const float*)d_in[9];
    const float* blin   = (const float*)d_in[10];
    float* out = (float*)d_out;

    cudaFuncSetAttribute(lstm_fwd_kernel,
                         cudaFuncAttributeMaxDynamicSharedMemorySize,
                         (int)sizeof(Smem));

    lstm_fwd_kernel<<<B_SZ, 256, sizeof(Smem)>>>(x, Wih_f, Whh_f, bih_f, bhh_f);
    lstm_bwd_out_kernel<<<B_SZ, 256>>>(x, Wih_b, bih_b, bhh_b, Wlin, blin, out);
}

// round 14
// speedup vs baseline: 1.2653x; 1.2653x over previous
#include <cuda_runtime.h>

#define T_SEQ 2048
#define I_IN 7
#define H_DIM 64
#define G_DIM 256   // 4*H
#define B_SZ 256
#define O_DIM 3

using u64 = unsigned long long;

// ---------- packed f32x2 helpers (Blackwell FFMA2 path) ----------
__device__ __forceinline__ u64 pack2(float lo, float hi) {
    u64 r;
    asm("mov.b64 %0, {%1, %2};" : "=l"(r) : "f"(lo), "f"(hi));
    return r;
}
__device__ __forceinline__ void unpack2(u64 v, float& lo, float& hi) {
    asm("mov.b64 {%0, %1}, %2;" : "=f"(lo), "=f"(hi) : "l"(v));
}
__device__ __forceinline__ void ffma2(u64& acc, u64 a, u64 b) {
    asm("fma.rn.f32x2 %0, %1, %2, %0;" : "+l"(acc) : "l"(a), "l"(b));
}
__device__ __forceinline__ u64 add2(u64 a, u64 b) {
    u64 r;
    asm("add.rn.f32x2 %0, %1, %2;" : "=l"(r) : "l"(a), "l"(b));
    return r;
}

// ---------- activations ----------
__device__ __forceinline__ float tanh_fast(float x) {      // MUFU.TANH
    float r;
    asm("tanh.approx.f32 %0, %1;" : "=f"(r) : "f"(x));
    return r;
}
__device__ __forceinline__ float sigm(float x) {           // accurate, bwd kernel only
    return __fdividef(1.0f, 1.0f + __expf(-x));
}

// Forward final hidden state, written by kernel1 and read by kernel2.
__device__ float g_hF[B_SZ * H_DIM];

// ---------- shared memory (dynamic), one batch element per CTA ----------
struct Smem {
    float xs[T_SEQ + 1][8]; // xs[t][i], i<7 valid, [7] pad; row T_SEQ = zeros. 65568 B
    float hs[2][H_DIM];     // ping-pong h state.                                 512 B
};                          // total ~66 KB -> 2 CTAs/SM

__global__ void __launch_bounds__(128, 2)
lstm_fwd_kernel(const float* __restrict__ x,
                const float* __restrict__ W_ih,
                const float* __restrict__ W_hh,
                const float* __restrict__ b_ih,
                const float* __restrict__ b_hh) {
    extern __shared__ Smem sh[];
    Smem& s = sh[0];

    const int tid = threadIdx.x;
    const int b = blockIdx.x;
    const int w = tid >> 5;
    const int l = tid & 31;
    const int p = l >> 4;                 // 0: owns (i,f); 1: owns (g,o)
    const int unit = w * 16 + (l & 15);   // hidden unit 0..63
    const int rowA = (p ? 2 * H_DIM : 0) + unit;         // i or g
    const int rowB = (p ? 3 * H_DIM : H_DIM) + unit;     // f or o

    // ---- stage this batch element's x into smem (+ zero pad row) ----
    {
        const float* xb = x + (size_t)b * T_SEQ * I_IN;
        for (int idx = tid; idx < T_SEQ * I_IN; idx += 128) {
            int t = idx / I_IN;
            int i = idx - t * I_IN;
            s.xs[t][i] = xb[idx];
        }
        for (int t = tid; t <= T_SEQ; t += 128) s.xs[t][7] = 0.f;
        if (tid < I_IN) s.xs[T_SEQ][tid] = 0.f;
        if (tid < 2 * H_DIM) ((float*)s.hs)[tid] = 0.f;
    }

    // ---- per-thread weights in registers: two W_hh rows + two W_ih rows ----
    u64 WkA[32], WkB[32];
    {
        const ulonglong2* wpA = reinterpret_cast<const ulonglong2*>(W_hh + rowA * H_DIM);
        const ulonglong2* wpB = reinterpret_cast<const ulonglong2*>(W_hh + rowB * H_DIM);
#pragma unroll
        for (int q = 0; q < 16; q++) {
            ulonglong2 vA = wpA[q];
            WkA[2 * q] = vA.x; WkA[2 * q + 1] = vA.y;
            ulonglong2 vB = wpB[q];
            WkB[2 * q] = vB.x; WkB[2 * q + 1] = vB.y;
        }
    }
    u64 WiA[4], WiB[4];
    {
        float wa[8], wb[8];
#pragma unroll
        for (int i = 0; i < 7; i++) {
            wa[i] = W_ih[rowA * I_IN + i];
            wb[i] = W_ih[rowB * I_IN + i];
        }
        wa[7] = wb[7] = 0.f;
#pragma unroll
        for (int q = 0; q < 4; q++) {
            WiA[q] = pack2(wa[2 * q], wa[2 * q + 1]);
            WiB[q] = pack2(wb[2 * q], wb[2 * q + 1]);
        }
    }
    const float biasA = b_ih[rowA] + b_hh[rowA];
    const float biasB = b_ih[rowB] + b_hh[rowB];

    // activation params: sigmoid(z) = 0.5 + 0.5*tanh(0.5 z); tanh for g-row
    const float sA = p ? 1.0f : 0.5f;     // rowA: g (tanh) if p, else i (sigm)
    const float aA = p ? 1.0f : 0.5f;
    const float bA = p ? 0.0f : 0.5f;
    // rowB (f or o) is always sigmoid

    float c_state = 0.f;                  // valid on p==0 lanes

    __syncthreads();

    // input projection + bias (packed along i)
    auto iproj = [&](int t, const u64* W, float bias) -> float {
        u64 acc = 0ull;
        const ulonglong2* xp = reinterpret_cast<const ulonglong2*>(s.xs[t]);
        ulonglong2 v0 = xp[0], v1 = xp[1];
        ffma2(acc, W[0], v0.x);
        ffma2(acc, W[1], v0.y);
        ffma2(acc, W[2], v1.x);
        ffma2(acc, W[3], v1.y);
        float lo, hi;
        unpack2(acc, lo, hi);
        return (lo + hi) + bias;
    };

    float accA = iproj(0, WiA, biasA);
    float accB = iproj(0, WiB, biasB);

    for (int t = 0; t < T_SEQ; t++) {
        // ---- two recurrent dots, 4 accumulators each (chain = 8 FFMA2) ----
        // accX folded into accumulator 0's low lane.
        u64 a0 = pack2(accA, 0.f), a1 = 0ull, a2 = 0ull, a3 = 0ull;
        u64 b0 = pack2(accB, 0.f), b1 = 0ull, b2 = 0ull, b3 = 0ull;
        const ulonglong2* hp = reinterpret_cast<const ulonglong2*>(s.hs[t & 1]);
#pragma unroll
        for (int q = 0; q < 4; q++) {
            ulonglong2 v0 = hp[4 * q + 0];
            ulonglong2 v1 = hp[4 * q + 1];
            ulonglong2 v2 = hp[4 * q + 2];
            ulonglong2 v3 = hp[4 * q + 3];
            ffma2(a0, WkA[8 * q + 0], v0.x);
            ffma2(a0, WkA[8 * q + 1], v0.y);
            ffma2(b0, WkB[8 * q + 0], v0.x);
            ffma2(b0, WkB[8 * q + 1], v0.y);
            ffma2(a1, WkA[8 * q + 2], v1.x);
            ffma2(a1, WkA[8 * q + 3], v1.y);
            ffma2(b1, WkB[8 * q + 2], v1.x);
            ffma2(b1, WkB[8 * q + 3], v1.y);
            ffma2(a2, WkA[8 * q + 4], v2.x);
            ffma2(a2, WkA[8 * q + 5], v2.y);
            ffma2(b2, WkB[8 * q + 4], v2.x);
            ffma2(b2, WkB[8 * q + 5], v2.y);
            ffma2(a3, WkA[8 * q + 6], v3.x);
            ffma2(a3, WkA[8 * q + 7], v3.y);
            ffma2(b3, WkB[8 * q + 6], v3.x);
            ffma2(b3, WkB[8 * q + 7], v3.y);
        }
        float al, ah, bl, bh;
        unpack2(add2(add2(a0, a1), add2(a2, a3)), al, ah);
        unpack2(add2(add2(b0, b1), add2(b2, b3)), bl, bh);
        float zA = al + ah;
        float zB = bl + bh;

        // ---- activations (p=0: i,f ; p=1: g,o) ----
        float actA = fmaf(aA, tanh_fast(sA * zA), bA);
        float actB = fmaf(0.5f, tanh_fast(0.5f * zB), 0.5f);

        // ---- pair exchange: p=0 receives (g, o) from its xor-16 partner ----
        float gv = __shfl_xor_sync(0xFFFFFFFFu, actA, 16);
        float ov = __shfl_xor_sync(0xFFFFFFFFu, actB, 16);

        // ---- cell + hidden update FIRST (publish h as early as possible) ----
        if (p == 0) {
            c_state = fmaf(actB, c_state, actA * gv);    // f*c + i*g
            s.hs[(t + 1) & 1][unit] = ov * tanh_fast(c_state);
        }

        // ---- next-step input projections (after h-store, off the z path) ----
        accA = iproj(t + 1, WiA, biasA);   // row T_SEQ is zero-padded
        accB = iproj(t + 1, WiB, biasB);

        __syncthreads();   // single barrier per step
    }

    // final h is in buffer T_SEQ & 1 == 0
    if (tid < H_DIM) g_hF[b * H_DIM + tid] = s.hs[0][tid];
}

// One backward LSTM step (from zero state on x[:,T-1,:]) + final linear.
__global__ void __launch_bounds__(256)
lstm_bwd_out_kernel(const float* __restrict__ x,
                    const float* __restrict__ W_ih_b,
                    const float* __restrict__ b_ih_b,
                    const float* __restrict__ b_hh_b,
                    const float* __restrict__ W_lin,
                    const float* __restrict__ b_lin,
                    float* __restrict__ out) {
    __shared__ float zs[G_DIM];
    __shared__ float hb[H_DIM];
    const int b = blockIdx.x;
    const int g = threadIdx.x;

    const float* xt = x + ((size_t)b * T_SEQ + (T_SEQ - 1)) * I_IN;
    float z = b_ih_b[g] + b_hh_b[g];
#pragma unroll
    for (int i = 0; i < I_IN; i++) z += W_ih_b[g * I_IN + i] * xt[i];
    zs[g] = z;
    __syncthreads();

    if (g < H_DIM) {
        float ig = sigm(zs[g]);
        float gg = tanhf(zs[2 * H_DIM + g]);
        float og = sigm(zs[3 * H_DIM + g]);
        float c = ig * gg;              // f * c_prev = 0 at first step
        hb[g] = og * tanhf(c);
    }
    __syncthreads();

    if (g < O_DIM) {
        float acc = b_lin[g];
        const float* wrow = W_lin + g * (2 * H_DIM);
        const float* hf = g_hF + b * H_DIM;
#pragma unroll 8
        for (int j = 0; j < H_DIM; j++) acc += wrow[j] * hf[j];
#pragma unroll 8
        for (int j = 0; j < H_DIM; j++) acc += wrow[H_DIM + j] * hb[j];
        out[b * O_DIM + g] = acc;
    }
}

extern "C" void kernel_launch(void* const* d_in, const int* in_sizes, int n_in,
                              void* d_out, int out_size) {
    const float* x      = (const float*)d_in[0];
    const float* Wih_f  = (const float*)d_in[1];
    const float* Whh_f  = (const float*)d_in[2];
    const float* bih_f  = (const float*)d_in[3];
    const float* bhh_f  = (const float*)d_in[4];
    const float* Wih_b  = (const float*)d_in[5];
    const float* bih_b  = (const float*)d_in[7];
    const float* bhh_b  = (const float*)d_in[8];
    const float* Wlin   = (const float*)d_in[9];
    const float* blin   = (const float*)d_in[10];
    float* out = (float*)d_out;

    cudaFuncSetAttribute(lstm_fwd_kernel,
                         cudaFuncAttributeMaxDynamicSharedMemorySize,
                         (int)sizeof(Smem));

    lstm_fwd_kernel<<<B_SZ, 128, sizeof(Smem)>>>(x, Wih_f, Whh_f, bih_f, bhh_f);
    lstm_bwd_out_kernel<<<B_SZ, 256>>>(x, Wih_b, bih_b, bhh_b, Wlin, blin, out);
}

// round 15
// speedup vs baseline: 1.3225x; 1.0453x over previous
#include <cuda_runtime.h>

#define T_SEQ 2048
#define I_IN 7
#define H_DIM 64
#define G_DIM 256   // 4*H
#define B_SZ 256
#define O_DIM 3

using u64 = unsigned long long;

// ---------- packed f32x2 helpers (Blackwell FFMA2 path) ----------
__device__ __forceinline__ u64 pack2(float lo, float hi) {
    u64 r;
    asm("mov.b64 %0, {%1, %2};" : "=l"(r) : "f"(lo), "f"(hi));
    return r;
}
__device__ __forceinline__ void unpack2(u64 v, float& lo, float& hi) {
    asm("mov.b64 {%0, %1}, %2;" : "=f"(lo), "=f"(hi) : "l"(v));
}
__device__ __forceinline__ void ffma2(u64& acc, u64 a, u64 b) {
    asm("fma.rn.f32x2 %0, %1, %2, %0;" : "+l"(acc) : "l"(a), "l"(b));
}
__device__ __forceinline__ u64 add2(u64 a, u64 b) {
    u64 r;
    asm("add.rn.f32x2 %0, %1, %2;" : "=l"(r) : "l"(a), "l"(b));
    return r;
}

// ---------- activations ----------
__device__ __forceinline__ float tanh_fast(float x) {      // MUFU.TANH
    float r;
    asm("tanh.approx.f32 %0, %1;" : "=f"(r) : "f"(x));
    return r;
}
__device__ __forceinline__ float sigm(float x) {           // accurate, bwd kernel only
    return __fdividef(1.0f, 1.0f + __expf(-x));
}

// Forward final hidden state, written by kernel1 and read by kernel2.
__device__ float g_hF[B_SZ * H_DIM];

// ---------- shared memory (dynamic), one batch element per CTA ----------
struct Smem {
    float xs[T_SEQ + 1][8]; // xs[t][i], i<7 valid, [7] pad; row T_SEQ = zeros.
    float hs[2][H_DIM];     // ping-pong h state.
};                          // total ~66 KB -> 2 CTAs/SM

__global__ void __launch_bounds__(128, 2)
lstm_fwd_kernel(const float* __restrict__ x,
                const float* __restrict__ W_ih,
                const float* __restrict__ W_hh,
                const float* __restrict__ b_ih,
                const float* __restrict__ b_hh) {
    extern __shared__ Smem sh[];
    Smem& s = sh[0];

    const int tid = threadIdx.x;
    const int b = blockIdx.x;
    const int w = tid >> 5;
    const int l = tid & 31;
    const int p = l >> 4;                 // 0: owns (i,f); 1: owns (g,o)
    const int unit = w * 16 + (l & 15);   // hidden unit 0..63
    const int rowA = (p ? 2 * H_DIM : 0) + unit;         // i or g
    const int rowB = (p ? 3 * H_DIM : H_DIM) + unit;     // f or o

    // ---- stage this batch element's x into smem (+ zero row at T_SEQ) ----
    {
        const float* xb = x + (size_t)b * T_SEQ * I_IN;
        for (int idx = tid; idx < T_SEQ * I_IN; idx += 128) {
            int t = idx / I_IN;
            int i = idx - t * I_IN;
            s.xs[t][i] = xb[idx];
        }
        for (int t = tid; t < T_SEQ; t += 128) s.xs[t][7] = 0.f;
        if (tid < 8) s.xs[T_SEQ][tid] = 0.f;
        if (tid < 2 * H_DIM) ((float*)s.hs)[tid] = 0.f;
    }

    // ---- per-thread weights in registers: two W_hh rows + two W_ih rows ----
    u64 WkA[32], WkB[32];
    {
        const ulonglong2* wpA = reinterpret_cast<const ulonglong2*>(W_hh + rowA * H_DIM);
        const ulonglong2* wpB = reinterpret_cast<const ulonglong2*>(W_hh + rowB * H_DIM);
#pragma unroll
        for (int q = 0; q < 16; q++) {
            ulonglong2 vA = wpA[q];
            WkA[2 * q] = vA.x; WkA[2 * q + 1] = vA.y;
            ulonglong2 vB = wpB[q];
            WkB[2 * q] = vB.x; WkB[2 * q + 1] = vB.y;
        }
    }
    u64 WiA[4], WiB[4];
    {
        float wa[8], wb[8];
#pragma unroll
        for (int i = 0; i < 7; i++) {
            wa[i] = W_ih[rowA * I_IN + i];
            wb[i] = W_ih[rowB * I_IN + i];
        }
        wa[7] = wb[7] = 0.f;
#pragma unroll
        for (int q = 0; q < 4; q++) {
            WiA[q] = pack2(wa[2 * q], wa[2 * q + 1]);
            WiB[q] = pack2(wb[2 * q], wb[2 * q + 1]);
        }
    }
    const float biasA = b_ih[rowA] + b_hh[rowA];
    const float biasB = b_ih[rowB] + b_hh[rowB];

    // activation params: sigmoid(z) = 0.5 + 0.5*tanh(0.5 z); tanh for g-row
    const float sA = p ? 1.0f : 0.5f;     // rowA: g (tanh) if p, else i (sigm)
    const float aA = p ? 1.0f : 0.5f;
    const float bA = p ? 0.0f : 0.5f;
    // rowB (f or o) is always sigmoid

    float c_state = 0.f;                  // valid on p==0 lanes

    __syncthreads();

    // input projection + bias (packed along i)
    auto iproj = [&](int t, const u64* W, float bias) -> float {
        u64 acc = 0ull;
        const ulonglong2* xp = reinterpret_cast<const ulonglong2*>(s.xs[t]);
        ulonglong2 v0 = xp[0], v1 = xp[1];
        ffma2(acc, W[0], v0.x);
        ffma2(acc, W[1], v0.y);
        ffma2(acc, W[2], v1.x);
        ffma2(acc, W[3], v1.y);
        float lo, hi;
        unpack2(acc, lo, hi);
        return (lo + hi) + bias;
    };

    float accA = iproj(0, WiA, biasA);
    float accB = iproj(0, WiB, biasB);

    for (int t = 0; t < T_SEQ; t++) {
        // ---- next-step input projections FIRST: independent work that fills
        //      the latency shadow of the h-loads at the head of the dot ----
        float nextA = iproj(t + 1, WiA, biasA);   // row T_SEQ is zeros
        float nextB = iproj(t + 1, WiB, biasB);

        // ---- two recurrent dots (2 accumulators each), read h buffer t&1 ----
        u64 a0 = 0ull, a1 = 0ull, b0 = 0ull, b1 = 0ull;
        const ulonglong2* hp = reinterpret_cast<const ulonglong2*>(s.hs[t & 1]);
#pragma unroll
        for (int q = 0; q < 8; q++) {
            ulonglong2 v0 = hp[2 * q];
            ulonglong2 v1 = hp[2 * q + 1];
            ffma2(a0, WkA[4 * q + 0], v0.x);
            ffma2(a0, WkA[4 * q + 1], v0.y);
            ffma2(b0, WkB[4 * q + 0], v0.x);
            ffma2(b0, WkB[4 * q + 1], v0.y);
            ffma2(a1, WkA[4 * q + 2], v1.x);
            ffma2(a1, WkA[4 * q + 3], v1.y);
            ffma2(b1, WkB[4 * q + 2], v1.x);
            ffma2(b1, WkB[4 * q + 3], v1.y);
        }
        float al, ah, bl, bh;
        unpack2(add2(a0, a1), al, ah);
        unpack2(add2(b0, b1), bl, bh);
        float zA = accA + (al + ah);
        float zB = accB + (bl + bh);

        // ---- activations (p=0: i,f ; p=1: g,o) ----
        float actA = fmaf(aA, tanh_fast(sA * zA), bA);
        float actB = fmaf(0.5f, tanh_fast(0.5f * zB), 0.5f);

        // ---- pair exchange: p=0 receives (g, o) from its xor-16 partner ----
        float gv = __shfl_xor_sync(0xFFFFFFFFu, actA, 16);
        float ov = __shfl_xor_sync(0xFFFFFFFFu, actB, 16);

        // ---- cell + hidden update immediately (earliest h publication) ----
        if (p == 0) {
            c_state = fmaf(actB, c_state, actA * gv);    // f*c + i*g
            s.hs[(t + 1) & 1][unit] = ov * tanh_fast(c_state);
        }

        accA = nextA;
        accB = nextB;

        __syncthreads();   // single barrier per step
    }

    // final h is in buffer T_SEQ & 1 == 0
    if (tid < H_DIM) g_hF[b * H_DIM + tid] = s.hs[0][tid];
}

// One backward LSTM step (from zero state on x[:,T-1,:]) + final linear.
__global__ void __launch_bounds__(256)
lstm_bwd_out_kernel(const float* __restrict__ x,
                    const float* __restrict__ W_ih_b,
                    const float* __restrict__ b_ih_b,
                    const float* __restrict__ b_hh_b,
                    const float* __restrict__ W_lin,
                    const float* __restrict__ b_lin,
                    float* __restrict__ out) {
    __shared__ float zs[G_DIM];
    __shared__ float hb[H_DIM];
    const int b = blockIdx.x;
    const int g = threadIdx.x;

    const float* xt = x + ((size_t)b * T_SEQ + (T_SEQ - 1)) * I_IN;
    float z = b_ih_b[g] + b_hh_b[g];
#pragma unroll
    for (int i = 0; i < I_IN; i++) z += W_ih_b[g * I_IN + i] * xt[i];
    zs[g] = z;
    __syncthreads();

    if (g < H_DIM) {
        float ig = sigm(zs[g]);
        float gg = tanhf(zs[2 * H_DIM + g]);
        float og = sigm(zs[3 * H_DIM + g]);
        float c = ig * gg;              // f * c_prev = 0 at first step
        hb[g] = og * tanhf(c);
    }
    __syncthreads();

    if (g < O_DIM) {
        float acc = b_lin[g];
        const float* wrow = W_lin + g * (2 * H_DIM);
        const float* hf = g_hF + b * H_DIM;
#pragma unroll 8
        for (int j = 0; j < H_DIM; j++) acc += wrow[j] * hf[j];
#pragma unroll 8
        for (int j = 0; j < H_DIM; j++) acc += wrow[H_DIM + j] * hb[j];
        out[b * O_DIM + g] = acc;
    }
}

extern "C" void kernel_launch(void* const* d_in, const int* in_sizes, int n_in,
                              void* d_out, int out_size) {
    const float* x      = (const float*)d_in[0];
    const float* Wih_f  = (const float*)d_in[1];
    const float* Whh_f  = (const float*)d_in[2];
    const float* bih_f  = (const float*)d_in[3];
    const float* bhh_f  = (const float*)d_in[4];
    const float* Wih_b  = (const float*)d_in[5];
    const float* bih_b  = (const float*)d_in[7];
    const float* bhh_b  = (const float*)d_in[8];
    const float* Wlin   = (const float*)d_in[9];
    const float* blin   = (const float*)d_in[10];
    float* out = (float*)d_out;

    cudaFuncSetAttribute(lstm_fwd_kernel,
                         cudaFuncAttributeMaxDynamicSharedMemorySize,
                         (int)sizeof(Smem));

    lstm_fwd_kernel<<<B_SZ, 128, sizeof(Smem)>>>(x, Wih_f, Whh_f, bih_f, bhh_f);
    lstm_bwd_out_kernel<<<B_SZ, 256>>>(x, Wih_b, bih_b, bhh_b, Wlin, blin, out);
}